// round 9
// baseline (speedup 1.0000x reference)
#include <cuda_runtime.h>
#include <stdint.h>

#define NP     65536
#define NA     1024
#define NMAX   512
#define GRID   100
#define CELLS  (GRID * GRID)
#define CAP    48          // max pts/cell; lambda=6.55 => P(>48) < 1e-20
#define TPB    256         // threads per anchor block

// Scratch (allocation-free rule: __device__ globals)
__device__ int    g_cnt[CELLS];
__device__ float4 g_bin[CELLS * CAP];   // packed (x, y, z, (float)pointIdx); idx<=65535 exact in f32

static __device__ __forceinline__ int cell_of(float x, float y) {
    int gx = (int)floorf(x);          // cell size = 1.0
    int gy = (int)floorf(y);
    gx = min(GRID - 1, max(0, gx));
    gy = min(GRID - 1, max(0, gy));
    return gy * GRID + gx;
}

// 1 point per thread: 65536 threads. Packs full record into the bin.
__global__ void k_bin(const float* __restrict__ pts) {
    int p = blockIdx.x * blockDim.x + threadIdx.x;
    float x = __ldg(&pts[p * 3 + 0]);
    float y = __ldg(&pts[p * 3 + 1]);
    float z = __ldg(&pts[p * 3 + 2]);
    int c = cell_of(x, y);
    int pos = atomicAdd(&g_cnt[c], 1);
    if (pos < CAP) g_bin[c * CAP + pos] = make_float4(x, y, z, (float)p);
}

// One block per anchor. 7 blocks/SM => 1036 concurrent, SINGLE WAVE.
// Coords cached in shared at test time => phase B has zero global loads.
__global__ void __launch_bounds__(TPB, 7) k_anchor(
    const float* __restrict__ anch,
    float* __restrict__ out,
    float* __restrict__ counts_out)
{
    int a = blockIdx.x;
    int tid = threadIdx.x;
    int lane = tid & 31;

    // Anchor row = 6 floats at byte offset a*24 (8-aligned): 3 broadcast LDG.64.
    const float2* arow = (const float2*)(anch + a * 6);
    float2 f01 = __ldg(&arow[0]);   // cx, cy
    float2 f23 = __ldg(&arow[1]);   // cz, w
    float2 f45 = __ldg(&arow[2]);   // l, h
    float cx = f01.x, cy = f01.y;
    float w = f23.y, l = f45.x, h = f45.y;
    float hw = w * 0.5f, hl = l * 0.5f;
    float x0 = cx - hw, x1 = cx + hw;
    float y0 = cy - hl, y1 = cy + hl;

    int gx0 = max(0, (int)floorf(x0));
    int gx1 = min(GRID - 1, (int)floorf(x1));
    int gy0 = max(0, (int)floorf(y0));
    int gy1 = min(GRID - 1, (int)floorf(y1));
    int ncx = gx1 - gx0 + 1;
    int ncy = gy1 - gy0 + 1;
    int ncells = ncx * ncy;   // <= 36 (w,l <= 5, cell = 1.0)

    __shared__ int           s_base[40];      // g_bin base per covered cell
    __shared__ int           s_ccnt[40];
    __shared__ int           s_off[40];       // exclusive offset per cell
    __shared__ int           s_total;
    __shared__ unsigned char s_cid[36 * CAP]; // candidate -> covered-cell id
    __shared__ float         s_key[NMAX];     // point index as float (exact)
    __shared__ float         s_px[NMAX], s_py[NMAX], s_pz[NMAX];
    __shared__ int           s_count;

    if (tid == 0) s_count = 0;
    if (tid < ncells) {
        int cgx = gx0 + (tid % ncx);
        int cgy = gy0 + (tid / ncx);
        int c = cgy * GRID + cgx;
        s_base[tid] = c * CAP;
        s_ccnt[tid] = min(g_cnt[c], CAP);
    }
    __syncthreads();                                   // (1)

    if (tid < ncells) {
        int off = 0;
        for (int j = 0; j < tid; j++) off += s_ccnt[j];
        s_off[tid] = off;
        int cnt = s_ccnt[tid];
        for (int k = 0; k < cnt; k++) s_cid[off + k] = (unsigned char)tid;
        if (tid == ncells - 1) s_total = off + cnt;
    }
    __syncthreads();                                   // (2)

    int total = s_total;

    // Phase A: test candidates (usually one pass: total ~230 < 256), warp-
    // aggregated compaction of key AND coords into shared (order-free).
    for (int i0 = 0; i0 < total; i0 += TPB) {
        int i = i0 + tid;
        bool hit = false;
        float4 r = make_float4(0.f, 0.f, 0.f, 0.f);
        if (i < total) {
            int j = (int)s_cid[i];
            r = __ldg(&g_bin[s_base[j] + (i - s_off[j])]);
            hit = (r.x >= x0 && r.x <= x1 && r.y >= y0 && r.y <= y1 &&
                   r.z >= 0.0f && r.z <= h);
        }
        unsigned bal = __ballot_sync(0xFFFFFFFFu, hit);
        int nb = __popc(bal);
        int base = 0;
        if (lane == 0 && nb) base = atomicAdd(&s_count, nb);
        base = __shfl_sync(0xFFFFFFFFu, base, 0);
        if (hit) {
            int pos = base + __popc(bal & ((1u << lane) - 1u));
            if (pos < NMAX) {
                s_key[pos] = r.w;
                s_px[pos] = r.x; s_py[pos] = r.y; s_pz[pos] = r.z;
            }
        }
    }
    __syncthreads();                                   // (3)

    int cnt = s_count;
    int m = min(cnt, NMAX);
    float* outa = out + (size_t)a * NMAX * 3;

    // Zero the tail [3m, 1536): scalar head up to 16B boundary, then STG.128.
    int limit = 3 * m;
    int head_end = (limit + 3) & ~3;          // first float4-aligned index >= limit
    if (tid < head_end - limit) outa[limit + tid] = 0.0f;
    {
        float4 z4 = make_float4(0.f, 0.f, 0.f, 0.f);
        float4* outa4 = (float4*)outa;        // out is 16B-aligned (a*6144 bytes)
        for (int q = (head_end >> 2) + tid; q < NMAX * 3 / 4; q += TPB) outa4[q] = z4;
    }

    // Rank-by-counting (broadcast LDS) + direct ranked store. No global loads.
    for (int s = tid; s < m; s += TPB) {
        float key = s_key[s];
        int r = 0;
        int j = 0;
        for (; j + 4 <= m; j += 4) {
            r += (s_key[j + 0] < key);
            r += (s_key[j + 1] < key);
            r += (s_key[j + 2] < key);
            r += (s_key[j + 3] < key);
        }
        for (; j < m; j++) r += (s_key[j] < key);
        outa[r * 3 + 0] = s_px[s] - cx;
        outa[r * 3 + 1] = s_py[s] - cy;
        outa[r * 3 + 2] = s_pz[s];
    }
    if (tid == 0) counts_out[a] = (float)cnt;
}

extern "C" void kernel_launch(void* const* d_in, const int* in_sizes, int n_in,
                              void* d_out, int out_size) {
    const float* pts  = (const float*)d_in[0];   // (65536, 3) f32
    const float* anch = (const float*)d_in[1];   // (1024, 6)  f32
    float* out = (float*)d_out;                  // 1024*512*3 f32, then 1024 counts
    float* counts_out = out + (size_t)NA * NMAX * 3;

    // Zero the cell counters via a memset node (graph-capturable async op).
    void* cnt_ptr = nullptr;
    cudaGetSymbolAddress(&cnt_ptr, g_cnt);
    cudaMemsetAsync(cnt_ptr, 0, CELLS * sizeof(int));

    k_bin<<<NP / 256, 256>>>(pts);
    k_anchor<<<NA, TPB>>>(anch, out, counts_out);
}